// round 7
// baseline (speedup 1.0000x reference)
#include <cuda_runtime.h>
#include <math.h>

// ---------------------------------------------------------------------------
// 2-layer LSTM, B=16, S=2048, I=256, H=512, fp32.
// Persistent kernel: 128 CTAs (1/SM), each owns 4 hidden units per layer
// (= 16 gate rows/layer). Weight slices live in SMEM for the whole run.
// One custom grid barrier per timestep (h0 broadcast); h1/c are covered
// transitively by the next step's barrier. f32x2 packed FMA inner loop.
// ---------------------------------------------------------------------------

#define BATCH 16
#define SEQ   2048
#define IDIM  256
#define HDIM  512
#define NCTA  128
#define NTHREADS 256
#define ROWS  16          // 4 units x 4 gates per CTA, per layer
#define UNITS 4
#define K0    768         // I + H
#define K1    1024        // H + H
#define P0    770         // padded pitch (bank-conflict-free for LDS.64)
#define P1    1026

// ---- global scratch (__device__ arrays: allocation-guard safe) ----
__device__ __align__(16) float g_h0[2][BATCH * HDIM];
__device__ __align__(16) float g_h1[2][BATCH * HDIM];
__device__ unsigned int g_bar_count = 0;
__device__ volatile unsigned int g_bar_epoch = 0;

// ---- grid barrier: arrive-count + monotone epoch (replay-safe) ----
__device__ __forceinline__ void grid_barrier(unsigned int target) {
    __syncthreads();
    if (threadIdx.x == 0) {
        __threadfence();
        unsigned int a = atomicAdd(&g_bar_count, 1u);
        if (a == NCTA - 1) {
            atomicExch(&g_bar_count, 0u);
            __threadfence();
            g_bar_epoch = target;                 // volatile store (release via fence)
        } else {
            while ((int)(g_bar_epoch - target) < 0) { }  // volatile spin
        }
        __threadfence();
    }
    __syncthreads();
}

// ---- packed f32x2 FMA helpers ----
__device__ __forceinline__ void ffma2(unsigned long long& acc,
                                      unsigned long long a,
                                      unsigned long long b) {
    asm("fma.rn.f32x2 %0, %1, %2, %0;" : "+l"(acc) : "l"(a), "l"(b));
}
__device__ __forceinline__ float u2sum(unsigned long long v) {
    float lo, hi;
    asm("mov.b64 {%0,%1}, %2;" : "=f"(lo), "=f"(hi) : "l"(v));
    return lo + hi;
}

// ---- per-CTA GEMM: C[16 rows x 16 batch] += W_slice @ A, split-K by 4 ----
// 256 threads = 4 k-groups x (8 thread-rows x 8 thread-cols), 2x2 register tile,
// f32x2 over the k dimension. Partials land in sGp[4][16][16].
template <int K, int PITCH>
__device__ __forceinline__ void gemm_slice(const float* __restrict__ sW,
                                           const float* __restrict__ sA,
                                           float* __restrict__ sGp) {
    const int tid = threadIdx.x;
    const int kg  = tid >> 6;          // 0..3  split-K group
    const int t64 = tid & 63;
    const int tr  = t64 >> 3;          // 0..7 -> rows 2tr, 2tr+1
    const int tc  = t64 & 7;           // 0..7 -> batches 2tc, 2tc+1
    constexpr int KPG = (K / 2) / 4;   // k-pairs per group (96 or 128)

    const unsigned long long* w0 =
        (const unsigned long long*)(sW + (2 * tr) * PITCH) + kg * KPG;
    const unsigned long long* w1 =
        (const unsigned long long*)(sW + (2 * tr + 1) * PITCH) + kg * KPG;
    const unsigned long long* a0 =
        (const unsigned long long*)(sA + (2 * tc) * PITCH) + kg * KPG;
    const unsigned long long* a1 =
        (const unsigned long long*)(sA + (2 * tc + 1) * PITCH) + kg * KPG;

    unsigned long long acc00 = 0ull, acc01 = 0ull, acc10 = 0ull, acc11 = 0ull;

#pragma unroll 8
    for (int kp = 0; kp < KPG; ++kp) {
        unsigned long long wa = w0[kp];
        unsigned long long wb = w1[kp];
        unsigned long long xa = a0[kp];
        unsigned long long xb = a1[kp];
        ffma2(acc00, wa, xa);
        ffma2(acc01, wa, xb);
        ffma2(acc10, wb, xa);
        ffma2(acc11, wb, xb);
    }

    float* dst = sGp + kg * 256;
    dst[(2 * tr) * 16 + 2 * tc]         = u2sum(acc00);
    dst[(2 * tr) * 16 + 2 * tc + 1]     = u2sum(acc01);
    dst[(2 * tr + 1) * 16 + 2 * tc]     = u2sum(acc10);
    dst[(2 * tr + 1) * 16 + 2 * tc + 1] = u2sum(acc11);
}

__device__ __forceinline__ float sigmoidf_(float v) {
    return 1.0f / (1.0f + expf(-v));
}

__global__ void __launch_bounds__(NTHREADS, 1)
lstm2_persistent(const float* __restrict__ x,
                 const float* __restrict__ W0,
                 const float* __restrict__ b0,
                 const float* __restrict__ W1,
                 const float* __restrict__ b1,
                 float* __restrict__ out) {
    extern __shared__ float smem[];
    float* sW0 = smem;                       // 16 * 770
    float* sW1 = sW0 + ROWS * P0;            // 16 * 1026
    float* sA  = sW1 + ROWS * P1;            // 16 * 1026 (shared A buffer)
    float* sGp = sA + BATCH * P1;            // 4 * 256 split-K partials
    float* sB0 = sGp + 4 * 256;              // 16
    float* sB1 = sB0 + 16;                   // 16

    const int m   = blockIdx.x;
    const int tid = threadIdx.x;
    const int u0  = m * UNITS;               // first hidden unit owned

    // ---- load persistent weight slices (row r = u*4 + gate) ----
    for (int idx = tid; idx < ROWS * (K0 / 2); idx += NTHREADS) {
        int r = idx / (K0 / 2), k2 = idx % (K0 / 2);
        int gg = r & 3, u = r >> 2;
        int grow = gg * HDIM + u0 + u;
        ((float2*)(sW0 + r * P0))[k2] =
            ((const float2*)(W0 + (size_t)grow * K0))[k2];
    }
    for (int idx = tid; idx < ROWS * (K1 / 2); idx += NTHREADS) {
        int r = idx / (K1 / 2), k2 = idx % (K1 / 2);
        int gg = r & 3, u = r >> 2;
        int grow = gg * HDIM + u0 + u;
        ((float2*)(sW1 + r * P1))[k2] =
            ((const float2*)(W1 + (size_t)grow * K1))[k2];
    }
    if (tid < ROWS) {
        int gg = tid & 3, u = tid >> 2;
        sB0[tid] = b0[gg * HDIM + u0 + u];
        sB1[tid] = b1[gg * HDIM + u0 + u];
    }

    // cell-update role for threads 0..63
    const int uu = tid >> 4;                 // 0..3 unit
    const int bb = tid & 15;                 // 0..15 batch
    float c0 = 0.f, c1 = 0.f, h0r = 0.f, h1r = 0.f;

    // zero initial h buffers (slot 1 = "t = -1") for own slice
    if (tid < 64) {
        g_h0[1][bb * HDIM + u0 + uu] = 0.f;
        g_h1[1][bb * HDIM + u0 + uu] = 0.f;
        __threadfence();
    }

    unsigned int ebase = 0;
    if (tid == 0) ebase = g_bar_epoch;       // stable: no bump until all arrive
    grid_barrier(ebase + 1);                 // publish zero-init

    for (int t = 0; t < SEQ; ++t) {
        const int cur = t & 1, prv = cur ^ 1;

        // ---- Phase A: stage [x_t ; h0(t-1)] as [b][k] (pitch P0) ----
        {
            const float* xrow = x + (size_t)t * IDIM;
            for (int idx = tid; idx < BATCH * (K0 / 2); idx += NTHREADS) {
                int b = idx / (K0 / 2), k = (idx % (K0 / 2)) * 2;
                float2 v;
                if (k < IDIM)
                    v = *(const float2*)(xrow + (size_t)b * SEQ * IDIM + k);
                else
                    v = *(const float2*)(g_h0[prv] + b * HDIM + (k - IDIM));
                *(float2*)(sA + b * P0 + k) = v;
            }
        }
        __syncthreads();
        gemm_slice<K0, P0>(sW0, sA, sGp);
        __syncthreads();

        if (tid < 64) {
            float g4[4];
#pragma unroll
            for (int gg = 0; gg < 4; ++gg) {
                int o = (uu * 4 + gg) * 16 + bb;
                g4[gg] = sGp[o] + sGp[256 + o] + sGp[512 + o] + sGp[768 + o] +
                         sB0[uu * 4 + gg];
            }
            float ig = sigmoidf_(g4[0]);
            float fg = sigmoidf_(g4[1]);
            float cg = tanhf(g4[2]);
            float og = sigmoidf_(g4[3]);
            c0  = fg * c0 + ig * cg;
            h0r = og * tanhf(c0);
            g_h0[cur][bb * HDIM + u0 + uu] = h0r;
            __threadfence();
        }
        grid_barrier(ebase + 2 + (unsigned)t);   // h0(t) visible everywhere

        // ---- Phase B: stage [h0(t) ; h1(t-1)] (pitch P1) ----
        for (int idx = tid; idx < BATCH * (K1 / 2); idx += NTHREADS) {
            int b = idx / (K1 / 2), k = (idx % (K1 / 2)) * 2;
            float2 v;
            if (k < HDIM)
                v = *(const float2*)(g_h0[cur] + b * HDIM + k);
            else
                v = *(const float2*)(g_h1[prv] + b * HDIM + (k - HDIM));
            *(float2*)(sA + b * P1 + k) = v;
        }
        __syncthreads();
        gemm_slice<K1, P1>(sW1, sA, sGp);
        __syncthreads();

        if (tid < 64) {
            float g4[4];
#pragma unroll
            for (int gg = 0; gg < 4; ++gg) {
                int o = (uu * 4 + gg) * 16 + bb;
                g4[gg] = sGp[o] + sGp[256 + o] + sGp[512 + o] + sGp[768 + o] +
                         sB1[uu * 4 + gg];
            }
            float ig = sigmoidf_(g4[0]);
            float fg = sigmoidf_(g4[1]);
            float cg = tanhf(g4[2]);
            float og = sigmoidf_(g4[3]);
            c1  = fg * c1 + ig * cg;
            h1r = og * tanhf(c1);
            g_h1[cur][bb * HDIM + u0 + uu] = h1r;
            out[((size_t)bb * SEQ + t) * HDIM + u0 + uu] = h1r;
            __threadfence();
        }
        // B(t) -> A(t+1) needs no barrier: A(t+1) touches neither h1 nor sGp
        // before the next __syncthreads, and writes a different h0 slot whose
        // readers all finished before grid_barrier(t).
        __syncthreads();
    }

    // ---- final (h, c) outputs: [2,B,H] each, after outputs[B,S,H] ----
    if (tid < 64) {
        const size_t OH = (size_t)BATCH * SEQ * HDIM;
        const size_t BH = (size_t)BATCH * HDIM;
        const size_t o  = (size_t)bb * HDIM + u0 + uu;
        out[OH + 0 * BH + o] = h0r;   // h layer 0
        out[OH + 1 * BH + o] = h1r;   // h layer 1
        out[OH + 2 * BH + o] = c0;    // c layer 0
        out[OH + 3 * BH + o] = c1;    // c layer 1
    }
}

extern "C" void kernel_launch(void* const* d_in, const int* in_sizes, int n_in,
                              void* d_out, int out_size) {
    const float* x  = (const float*)d_in[0];
    const float* W0 = (const float*)d_in[1];
    const float* b0 = (const float*)d_in[2];
    const float* W1 = (const float*)d_in[3];
    const float* b1 = (const float*)d_in[4];
    float* out = (float*)d_out;

    const int smem_bytes =
        (ROWS * P0 + ROWS * P1 + BATCH * P1 + 4 * 256 + 32) * (int)sizeof(float);

    cudaFuncSetAttribute(lstm2_persistent,
                         cudaFuncAttributeMaxDynamicSharedMemorySize,
                         smem_bytes);

    lstm2_persistent<<<NCTA, NTHREADS, smem_bytes>>>(x, W0, b0, W1, b1, out);
}

// round 8
// speedup vs baseline: 1.1379x; 1.1379x over previous
#include <cuda_runtime.h>
#include <math.h>

// ---------------------------------------------------------------------------
// 2-layer LSTM, B=16, S=2048, I=256, H=512, fp32.
// Persistent kernel: 128 CTAs (1/SM), each owns 4 hidden units per layer
// (= 16 gate rows/layer). Weight slices pinned in SMEM for the whole run.
// One grid barrier per timestep (h0 broadcast); h1/c covered transitively.
// R7: 4x4 register tile, split-K=16 with interleaved k-groups
// (conflict-free LDS.64), padded partial slabs. Crossbar traffic /4.
// ---------------------------------------------------------------------------

#define BATCH 16
#define SEQ   2048
#define IDIM  256
#define HDIM  512
#define NCTA  128
#define NTHREADS 256
#define ROWS  16          // 4 units x 4 gates per CTA, per layer
#define UNITS 4
#define K0    768         // I + H
#define K1    1024        // H + H
#define P0    770         // pitch: even (8B align), P%8==2 -> tr banks {0,8,16,24}
#define P1    1026
#define KGRP  16          // split-K groups
#define SLAB  264         // padded partial slab (264%32==8 -> no STS conflict)

// ---- global scratch ----
__device__ __align__(16) float g_h0[2][BATCH * HDIM];
__device__ __align__(16) float g_h1[2][BATCH * HDIM];
__device__ unsigned int g_bar_count = 0;
__device__ volatile unsigned int g_bar_epoch = 0;

// ---- grid barrier: arrive-count + monotone epoch (replay-safe) ----
__device__ __forceinline__ void grid_barrier(unsigned int target) {
    __syncthreads();
    if (threadIdx.x == 0) {
        __threadfence();
        unsigned int a = atomicAdd(&g_bar_count, 1u);
        if (a == NCTA - 1) {
            atomicExch(&g_bar_count, 0u);
            __threadfence();
            g_bar_epoch = target;
        } else {
            while ((int)(g_bar_epoch - target) < 0) { }
        }
        __threadfence();
    }
    __syncthreads();
}

// ---- packed f32x2 FMA helpers ----
__device__ __forceinline__ void ffma2(unsigned long long& acc,
                                      unsigned long long a,
                                      unsigned long long b) {
    asm("fma.rn.f32x2 %0, %1, %2, %0;" : "+l"(acc) : "l"(a), "l"(b));
}
__device__ __forceinline__ float u2sum(unsigned long long v) {
    float lo, hi;
    asm("mov.b64 {%0,%1}, %2;" : "=f"(lo), "=f"(hi) : "l"(v));
    return lo + hi;
}

// ---- per-CTA GEMM: C[16 rows x 16 batch], 4x4 reg tile, split-K 16 ----
// tid -> kg = tid>>4 (0..15), tr = (tid&15)>>2 (rows 4tr..), tc = tid&3.
// k index interleaved: k-pair = kp*16 + kg  (kg stride = 8B = 2 banks, so the
// two kgs inside a warp never collide with the 4-row {0,8,16,24} bank set).
// Per kp: 8 LDS.64 (all 1-wavefront) + 16 FFMA2 = 32 MACs.
template <int K, int PITCH>
__device__ __forceinline__ void gemm16x16(const float* __restrict__ sW,
                                          const float* __restrict__ sA,
                                          float* __restrict__ sGp) {
    const int tid = threadIdx.x;
    const int kg  = tid >> 4;          // 0..15 split-K group
    const int t16 = tid & 15;
    const int tr  = t16 >> 2;          // 0..3 -> rows 4tr..4tr+3
    const int tc  = t16 & 3;           // 0..3 -> batches 4tc..4tc+3
    constexpr int KPG = (K / 2) / KGRP;   // 24 (K0) or 32 (K1)

    const unsigned long long* w0 = (const unsigned long long*)(sW + (4*tr+0)*PITCH) + kg;
    const unsigned long long* w1 = (const unsigned long long*)(sW + (4*tr+1)*PITCH) + kg;
    const unsigned long long* w2 = (const unsigned long long*)(sW + (4*tr+2)*PITCH) + kg;
    const unsigned long long* w3 = (const unsigned long long*)(sW + (4*tr+3)*PITCH) + kg;
    const unsigned long long* a0 = (const unsigned long long*)(sA + (4*tc+0)*PITCH) + kg;
    const unsigned long long* a1 = (const unsigned long long*)(sA + (4*tc+1)*PITCH) + kg;
    const unsigned long long* a2 = (const unsigned long long*)(sA + (4*tc+2)*PITCH) + kg;
    const unsigned long long* a3 = (const unsigned long long*)(sA + (4*tc+3)*PITCH) + kg;

    unsigned long long acc[4][4];
#pragma unroll
    for (int i = 0; i < 4; ++i)
#pragma unroll
        for (int j = 0; j < 4; ++j) acc[i][j] = 0ull;

#pragma unroll 4
    for (int kp = 0; kp < KPG; ++kp) {
        const int o = kp * KGRP;       // interleaved k stride: 16 u64 = 128B
        unsigned long long wv0 = w0[o], wv1 = w1[o], wv2 = w2[o], wv3 = w3[o];
        unsigned long long av0 = a0[o], av1 = a1[o], av2 = a2[o], av3 = a3[o];
        ffma2(acc[0][0], wv0, av0); ffma2(acc[0][1], wv0, av1);
        ffma2(acc[0][2], wv0, av2); ffma2(acc[0][3], wv0, av3);
        ffma2(acc[1][0], wv1, av0); ffma2(acc[1][1], wv1, av1);
        ffma2(acc[1][2], wv1, av2); ffma2(acc[1][3], wv1, av3);
        ffma2(acc[2][0], wv2, av0); ffma2(acc[2][1], wv2, av1);
        ffma2(acc[2][2], wv2, av2); ffma2(acc[2][3], wv2, av3);
        ffma2(acc[3][0], wv3, av0); ffma2(acc[3][1], wv3, av1);
        ffma2(acc[3][2], wv3, av2); ffma2(acc[3][3], wv3, av3);
    }

    float* dst = sGp + kg * SLAB;
#pragma unroll
    for (int i = 0; i < 4; ++i)
#pragma unroll
        for (int j = 0; j < 4; ++j)
            dst[(4*tr + i) * 16 + 4*tc + j] = u2sum(acc[i][j]);
}

__device__ __forceinline__ float sigmoidf_(float v) {
    return 1.0f / (1.0f + expf(-v));
}

__global__ void __launch_bounds__(NTHREADS, 1)
lstm2_persistent(const float* __restrict__ x,
                 const float* __restrict__ W0,
                 const float* __restrict__ b0,
                 const float* __restrict__ W1,
                 const float* __restrict__ b1,
                 float* __restrict__ out) {
    extern __shared__ float smem[];
    float* sW0 = smem;                       // 16 * 770
    float* sW1 = sW0 + ROWS * P0;            // 16 * 1026
    float* sA  = sW1 + ROWS * P1;            // 16 * 1026 (A buffer, both layers)
    float* sGp = sA + BATCH * P1;            // 16 * 264 split-K partials
    float* sG  = sGp + KGRP * SLAB;          // 256 reduced gates (+bias)
    float* sB0 = sG + 256;                   // 16
    float* sB1 = sB0 + 16;                   // 16

    const int m   = blockIdx.x;
    const int tid = threadIdx.x;
    const int u0  = m * UNITS;               // first hidden unit owned

    // ---- load persistent weight slices (row r = u*4 + gate) ----
    for (int idx = tid; idx < ROWS * (K0 / 2); idx += NTHREADS) {
        int r = idx / (K0 / 2), k2 = idx % (K0 / 2);
        int gg = r & 3, u = r >> 2;
        int grow = gg * HDIM + u0 + u;
        ((float2*)(sW0 + r * P0))[k2] =
            ((const float2*)(W0 + (size_t)grow * K0))[k2];
    }
    for (int idx = tid; idx < ROWS * (K1 / 2); idx += NTHREADS) {
        int r = idx / (K1 / 2), k2 = idx % (K1 / 2);
        int gg = r & 3, u = r >> 2;
        int grow = gg * HDIM + u0 + u;
        ((float2*)(sW1 + r * P1))[k2] =
            ((const float2*)(W1 + (size_t)grow * K1))[k2];
    }
    if (tid < ROWS) {
        int gg = tid & 3, u = tid >> 2;
        sB0[tid] = b0[gg * HDIM + u0 + u];
        sB1[tid] = b1[gg * HDIM + u0 + u];
    }

    // cell-update role for threads 0..63
    const int uu = tid >> 4;                 // 0..3 unit (valid when tid<64)
    const int bb = tid & 15;                 // 0..15 batch
    float c0 = 0.f, c1 = 0.f, h0r = 0.f, h1r = 0.f;

    if (tid < 64) {
        g_h0[1][bb * HDIM + u0 + uu] = 0.f;
        g_h1[1][bb * HDIM + u0 + uu] = 0.f;
        __threadfence();
    }

    unsigned int ebase = 0;
    if (tid == 0) ebase = g_bar_epoch;
    grid_barrier(ebase + 1);                 // publish zero-init

    for (int t = 0; t < SEQ; ++t) {
        const int cur = t & 1, prv = cur ^ 1;

        // ---- Phase A: stage [x_t ; h0(t-1)] as [b][k], pitch P0 ----
        {
            const float* xrow = x + (size_t)t * IDIM;
            for (int idx = tid; idx < BATCH * (K0 / 2); idx += NTHREADS) {
                int b = idx / (K0 / 2), k = (idx % (K0 / 2)) * 2;
                float2 v;
                if (k < IDIM)
                    v = *(const float2*)(xrow + (size_t)b * SEQ * IDIM + k);
                else
                    v = *(const float2*)(g_h0[prv] + b * HDIM + (k - IDIM));
                *(float2*)(sA + b * P0 + k) = v;
            }
        }
        __syncthreads();
        gemm16x16<K0, P0>(sW0, sA, sGp);
        __syncthreads();

        // reduce 16 split-K partials + bias (conflict-free: lanes contiguous)
        {
            float red = sB0[tid >> 4];
#pragma unroll
            for (int s = 0; s < KGRP; ++s) red += sGp[s * SLAB + tid];
            sG[tid] = red;
        }
        __syncthreads();

        if (tid < 64) {
            float ig = sigmoidf_(sG[(uu * 4 + 0) * 16 + bb]);
            float fg = sigmoidf_(sG[(uu * 4 + 1) * 16 + bb]);
            float cg = tanhf(sG[(uu * 4 + 2) * 16 + bb]);
            float og = sigmoidf_(sG[(uu * 4 + 3) * 16 + bb]);
            c0  = fg * c0 + ig * cg;
            h0r = og * tanhf(c0);
            g_h0[cur][bb * HDIM + u0 + uu] = h0r;
            __threadfence();
        }
        grid_barrier(ebase + 2 + (unsigned)t);   // h0(t) visible everywhere

        // ---- Phase B: stage [h0(t) ; h1(t-1)], pitch P1 ----
        for (int idx = tid; idx < BATCH * (K1 / 2); idx += NTHREADS) {
            int b = idx / (K1 / 2), k = (idx % (K1 / 2)) * 2;
            float2 v;
            if (k < HDIM)
                v = *(const float2*)(g_h0[cur] + b * HDIM + k);
            else
                v = *(const float2*)(g_h1[prv] + b * HDIM + (k - HDIM));
            *(float2*)(sA + b * P1 + k) = v;
        }
        __syncthreads();
        gemm16x16<K1, P1>(sW1, sA, sGp);
        __syncthreads();

        {
            float red = sB1[tid >> 4];
#pragma unroll
            for (int s = 0; s < KGRP; ++s) red += sGp[s * SLAB + tid];
            sG[tid] = red;
        }
        __syncthreads();

        if (tid < 64) {
            float ig = sigmoidf_(sG[(uu * 4 + 0) * 16 + bb]);
            float fg = sigmoidf_(sG[(uu * 4 + 1) * 16 + bb]);
            float cg = tanhf(sG[(uu * 4 + 2) * 16 + bb]);
            float og = sigmoidf_(sG[(uu * 4 + 3) * 16 + bb]);
            c1  = fg * c1 + ig * cg;
            h1r = og * tanhf(c1);
            g_h1[cur][bb * HDIM + u0 + uu] = h1r;
            out[((size_t)bb * SEQ + t) * HDIM + u0 + uu] = h1r;
            __threadfence();
        }
        // B(t) -> A(t+1): no grid barrier needed (transitively covered by
        // barrier(t+1)); sA/sG reuse is covered by the in-loop __syncthreads.
        __syncthreads();
    }

    // ---- final (h, c): [2,B,H] h then [2,B,H] c, after outputs[B,S,H] ----
    if (tid < 64) {
        const size_t OH = (size_t)BATCH * SEQ * HDIM;
        const size_t BH = (size_t)BATCH * HDIM;
        const size_t o  = (size_t)bb * HDIM + u0 + uu;
        out[OH + 0 * BH + o] = h0r;   // h layer 0
        out[OH + 1 * BH + o] = h1r;   // h layer 1
        out[OH + 2 * BH + o] = c0;    // c layer 0
        out[OH + 3 * BH + o] = c1;    // c layer 1
    }
}

extern "C" void kernel_launch(void* const* d_in, const int* in_sizes, int n_in,
                              void* d_out, int out_size) {
    const float* x  = (const float*)d_in[0];
    const float* W0 = (const float*)d_in[1];
    const float* b0 = (const float*)d_in[2];
    const float* W1 = (const float*)d_in[3];
    const float* b1 = (const float*)d_in[4];
    float* out = (float*)d_out;

    const int smem_floats = ROWS * P0 + ROWS * P1 + BATCH * P1 +
                            KGRP * SLAB + 256 + 32;
    const int smem_bytes = smem_floats * (int)sizeof(float);

    cudaFuncSetAttribute(lstm2_persistent,
                         cudaFuncAttributeMaxDynamicSharedMemorySize,
                         smem_bytes);

    lstm2_persistent<<<NCTA, NTHREADS, smem_bytes>>>(x, W0, b0, W1, b1, out);
}

// round 9
// speedup vs baseline: 1.3173x; 1.1577x over previous
#include <cuda_runtime.h>
#include <math.h>

// ---------------------------------------------------------------------------
// 2-layer LSTM, B=16, S=2048, I=256, H=512, fp32.
// Persistent kernel: 128 CTAs (1/SM), each owns 4 hidden units per layer.
// Weight slices pinned in SMEM for the whole run.
// R8: global barrier replaced by per-CTA release flags (monotone seqnums):
//   - no atomic contention (one writer per flag), acquire-polls in parallel
//   - flags double as double-buffer slot protection
//   - cell threads reduce split-K partials directly (one less syncthreads)
//   - h-state reads via __ldcg (L2-coherent; removes stale-L1 hazard)
// ---------------------------------------------------------------------------

#define BATCH 16
#define SEQ   2048
#define IDIM  256
#define HDIM  512
#define NCTA  128
#define NTHREADS 256
#define ROWS  16          // 4 units x 4 gates per CTA, per layer
#define UNITS 4
#define K0    768         // I + H
#define K1    1024        // H + H
#define P0    770         // pitch: P%8==2 -> 4-row bank set {0,8,16,24}
#define P1    1026
#define KGRP  16          // split-K groups
#define SLAB  264         // padded partial slab (264%32==8 -> no STS conflict)

// ---- global scratch ----
__device__ __align__(16) float g_h0[2][BATCH * HDIM];
__device__ __align__(16) float g_h1[2][BATCH * HDIM];
__device__ unsigned int g_f0[NCTA];     // per-CTA seq: h0(t) published => f0 = base+t+1
__device__ unsigned int g_f1[NCTA];     // per-CTA seq: h1(t) published => f1 = base+t+1
__device__ unsigned int g_bar_count = 0;
__device__ volatile unsigned int g_bar_epoch = 0;

// ---- acquire/release helpers ----
__device__ __forceinline__ unsigned int ld_acq(const unsigned int* p) {
    unsigned int v;
    asm volatile("ld.acquire.gpu.u32 %0, [%1];" : "=r"(v) : "l"(p) : "memory");
    return v;
}
__device__ __forceinline__ void st_rel(unsigned int* p, unsigned int v) {
    asm volatile("st.release.gpu.u32 [%0], %1;" :: "l"(p), "r"(v) : "memory");
}

// one-time entry barrier (publishes zero-init); replay-safe monotone epoch
__device__ __forceinline__ void entry_barrier() {
    unsigned int ebase = 0;
    if (threadIdx.x == 0) ebase = g_bar_epoch;
    __syncthreads();
    if (threadIdx.x == 0) {
        __threadfence();
        unsigned int a = atomicAdd(&g_bar_count, 1u);
        unsigned int target = ebase + 1;
        if (a == NCTA - 1) {
            atomicExch(&g_bar_count, 0u);
            __threadfence();
            g_bar_epoch = target;
        } else {
            while ((int)(g_bar_epoch - target) < 0) { }
        }
        __threadfence();
    }
    __syncthreads();
}

// wait until ALL per-CTA flags reach target (128 parallel acquire-polls)
__device__ __forceinline__ void wait_flags(unsigned int* f, unsigned int target) {
    if (threadIdx.x < NCTA) {
        while ((int)(ld_acq(&f[threadIdx.x]) - target) < 0) { }
    }
    __syncthreads();
}

// ---- packed f32x2 FMA helpers ----
__device__ __forceinline__ void ffma2(unsigned long long& acc,
                                      unsigned long long a,
                                      unsigned long long b) {
    asm("fma.rn.f32x2 %0, %1, %2, %0;" : "+l"(acc) : "l"(a), "l"(b));
}
__device__ __forceinline__ float u2sum(unsigned long long v) {
    float lo, hi;
    asm("mov.b64 {%0,%1}, %2;" : "=f"(lo), "=f"(hi) : "l"(v));
    return lo + hi;
}

// ---- per-CTA GEMM: C[16 rows x 16 batch], 4x4 reg tile, split-K 16 ----
template <int K, int PITCH>
__device__ __forceinline__ void gemm16x16(const float* __restrict__ sW,
                                          const float* __restrict__ sA,
                                          float* __restrict__ sGp) {
    const int tid = threadIdx.x;
    const int kg  = tid >> 4;          // 0..15 split-K group
    const int t16 = tid & 15;
    const int tr  = t16 >> 2;          // 0..3 -> rows 4tr..4tr+3
    const int tc  = t16 & 3;           // 0..3 -> batches 4tc..4tc+3
    constexpr int KPG = (K / 2) / KGRP;   // 24 (K0) or 32 (K1)

    const unsigned long long* w0 = (const unsigned long long*)(sW + (4*tr+0)*PITCH) + kg;
    const unsigned long long* w1 = (const unsigned long long*)(sW + (4*tr+1)*PITCH) + kg;
    const unsigned long long* w2 = (const unsigned long long*)(sW + (4*tr+2)*PITCH) + kg;
    const unsigned long long* w3 = (const unsigned long long*)(sW + (4*tr+3)*PITCH) + kg;
    const unsigned long long* a0 = (const unsigned long long*)(sA + (4*tc+0)*PITCH) + kg;
    const unsigned long long* a1 = (const unsigned long long*)(sA + (4*tc+1)*PITCH) + kg;
    const unsigned long long* a2 = (const unsigned long long*)(sA + (4*tc+2)*PITCH) + kg;
    const unsigned long long* a3 = (const unsigned long long*)(sA + (4*tc+3)*PITCH) + kg;

    unsigned long long acc[4][4];
#pragma unroll
    for (int i = 0; i < 4; ++i)
#pragma unroll
        for (int j = 0; j < 4; ++j) acc[i][j] = 0ull;

#pragma unroll 4
    for (int kp = 0; kp < KPG; ++kp) {
        const int o = kp * KGRP;       // interleaved split-K stride (128B)
        unsigned long long wv0 = w0[o], wv1 = w1[o], wv2 = w2[o], wv3 = w3[o];
        unsigned long long av0 = a0[o], av1 = a1[o], av2 = a2[o], av3 = a3[o];
        ffma2(acc[0][0], wv0, av0); ffma2(acc[0][1], wv0, av1);
        ffma2(acc[0][2], wv0, av2); ffma2(acc[0][3], wv0, av3);
        ffma2(acc[1][0], wv1, av0); ffma2(acc[1][1], wv1, av1);
        ffma2(acc[1][2], wv1, av2); ffma2(acc[1][3], wv1, av3);
        ffma2(acc[2][0], wv2, av0); ffma2(acc[2][1], wv2, av1);
        ffma2(acc[2][2], wv2, av2); ffma2(acc[2][3], wv2, av3);
        ffma2(acc[3][0], wv3, av0); ffma2(acc[3][1], wv3, av1);
        ffma2(acc[3][2], wv3, av2); ffma2(acc[3][3], wv3, av3);
    }

    float* dst = sGp + kg * SLAB;
#pragma unroll
    for (int i = 0; i < 4; ++i)
#pragma unroll
        for (int j = 0; j < 4; ++j)
            dst[(4*tr + i) * 16 + 4*tc + j] = u2sum(acc[i][j]);
}

__device__ __forceinline__ float sigmoidf_(float v) {
    return 1.0f / (1.0f + expf(-v));
}

__global__ void __launch_bounds__(NTHREADS, 1)
lstm2_persistent(const float* __restrict__ x,
                 const float* __restrict__ W0,
                 const float* __restrict__ b0,
                 const float* __restrict__ W1,
                 const float* __restrict__ b1,
                 float* __restrict__ out) {
    extern __shared__ float smem[];
    float* sW0 = smem;                       // 16 * 770
    float* sW1 = sW0 + ROWS * P0;            // 16 * 1026
    float* sA  = sW1 + ROWS * P1;            // 16 * 1026 (A buffer, both layers)
    float* sGp = sA + BATCH * P1;            // 16 * 264 split-K partials
    float* sB0 = sGp + KGRP * SLAB;          // 16
    float* sB1 = sB0 + 16;                   // 16

    const int m   = blockIdx.x;
    const int tid = threadIdx.x;
    const int u0  = m * UNITS;

    // ---- load persistent weight slices (row r = u*4 + gate) ----
    for (int idx = tid; idx < ROWS * (K0 / 2); idx += NTHREADS) {
        int r = idx / (K0 / 2), k2 = idx % (K0 / 2);
        int gg = r & 3, u = r >> 2;
        int grow = gg * HDIM + u0 + u;
        ((float2*)(sW0 + r * P0))[k2] =
            ((const float2*)(W0 + (size_t)grow * K0))[k2];
    }
    for (int idx = tid; idx < ROWS * (K1 / 2); idx += NTHREADS) {
        int r = idx / (K1 / 2), k2 = idx % (K1 / 2);
        int gg = r & 3, u = r >> 2;
        int grow = gg * HDIM + u0 + u;
        ((float2*)(sW1 + r * P1))[k2] =
            ((const float2*)(W1 + (size_t)grow * K1))[k2];
    }
    if (tid < ROWS) {
        int gg = tid & 3, u = tid >> 2;
        sB0[tid] = b0[gg * HDIM + u0 + u];
        sB1[tid] = b1[gg * HDIM + u0 + u];
    }

    const int uu = tid >> 4;                 // 0..3 unit (valid when tid<64)
    const int bb = tid & 15;                 // 0..15 batch
    float c0 = 0.f, c1 = 0.f, h0r = 0.f, h1r = 0.f;

    // replay-safe flag base: each CTA reads its OWN flag (all equal at entry)
    unsigned int fbase = g_f0[m];            // == g_f1[m]

    // zero initial h (slot 1 = "t = -1")
    if (tid < 64) {
        g_h0[1][bb * HDIM + u0 + uu] = 0.f;
        g_h1[1][bb * HDIM + u0 + uu] = 0.f;
    }
    entry_barrier();                          // publish zeros + fbase stability

    for (int t = 0; t < SEQ; ++t) {
        const int cur = t & 1, prv = cur ^ 1;
        const unsigned int seq = fbase + (unsigned)t;

        // ================= Phase A: gates0 = W0 @ [x_t ; h0(t-1)] ==========
        // stage x first (no dependency), overlaps any straggler wait
        {
            const float* xrow = x + (size_t)t * IDIM;
            for (int idx = tid; idx < BATCH * (IDIM / 2); idx += NTHREADS) {
                int b = idx >> 7, k = (idx & 127) * 2;      // IDIM/2 = 128
                *(float2*)(sA + b * P0 + k) =
                    *(const float2*)(xrow + (size_t)b * SEQ * IDIM + k);
            }
        }
        wait_flags(g_f0, seq);                // h0(t-1) visible (t=0: trivial)
        for (int idx = tid; idx < BATCH * (HDIM / 2); idx += NTHREADS) {
            int b = idx >> 8, k = (idx & 255) * 2;          // HDIM/2 = 256
            float2 v = __ldcg((const float2*)(g_h0[prv] + b * HDIM + k));
            *(float2*)(sA + b * P0 + IDIM + k) = v;
        }
        __syncthreads();
        gemm16x16<K0, P0>(sW0, sA, sGp);
        __syncthreads();

        if (tid < 64) {
            float g4[4];
#pragma unroll
            for (int gg = 0; gg < 4; ++gg) {
                float r = sB0[uu * 4 + gg];
                const int o = (uu * 4 + gg) * 16 + bb;
#pragma unroll
                for (int s = 0; s < KGRP; ++s) r += sGp[s * SLAB + o];
                g4[gg] = r;
            }
            float ig = sigmoidf_(g4[0]);
            float fg = sigmoidf_(g4[1]);
            float cg = tanhf(g4[2]);
            float og = sigmoidf_(g4[3]);
            c0  = fg * c0 + ig * cg;
            h0r = og * tanhf(c0);
            g_h0[cur][bb * HDIM + u0 + uu] = h0r;
            __threadfence();
            asm volatile("bar.sync 1, 64;" ::: "memory");   // just the 2 cell warps
            if (tid == 0) st_rel(&g_f0[m], seq + 1u);       // h0(t) published
        }

        // ================= Phase B: gates1 = W1 @ [h0(t) ; h1(t-1)] ========
        wait_flags(g_f1, seq);                // h1(t-1) (published long ago)
        for (int idx = tid; idx < BATCH * (HDIM / 2); idx += NTHREADS) {
            int b = idx >> 8, k = (idx & 255) * 2;
            float2 v = __ldcg((const float2*)(g_h1[prv] + b * HDIM + k));
            *(float2*)(sA + b * P1 + HDIM + k) = v;
        }
        wait_flags(g_f0, seq + 1u);           // hot wait: h0(t) from all CTAs
        for (int idx = tid; idx < BATCH * (HDIM / 2); idx += NTHREADS) {
            int b = idx >> 8, k = (idx & 255) * 2;
            float2 v = __ldcg((const float2*)(g_h0[cur] + b * HDIM + k));
            *(float2*)(sA + b * P1 + k) = v;
        }
        __syncthreads();
        gemm16x16<K1, P1>(sW1, sA, sGp);
        __syncthreads();

        if (tid < 64) {
            float g4[4];
#pragma unroll
            for (int gg = 0; gg < 4; ++gg) {
                float r = sB1[uu * 4 + gg];
                const int o = (uu * 4 + gg) * 16 + bb;
#pragma unroll
                for (int s = 0; s < KGRP; ++s) r += sGp[s * SLAB + o];
                g4[gg] = r;
            }
            float ig = sigmoidf_(g4[0]);
            float fg = sigmoidf_(g4[1]);
            float cg = tanhf(g4[2]);
            float og = sigmoidf_(g4[3]);
            c1  = fg * c1 + ig * cg;
            h1r = og * tanhf(c1);
            g_h1[cur][bb * HDIM + u0 + uu] = h1r;
            out[((size_t)bb * SEQ + t) * HDIM + u0 + uu] = h1r;
            __threadfence();
            asm volatile("bar.sync 1, 64;" ::: "memory");
            if (tid == 0) st_rel(&g_f1[m], seq + 1u);       // h1(t) published
        }
        // no trailing sync: next phase-A x-staging writes sA only, and the
        // pre-GEMM __syncthreads (which cell threads join) protects sGp.
    }

    // ---- final (h, c): [2,B,H] h then [2,B,H] c, after outputs[B,S,H] ----
    if (tid < 64) {
        const size_t OH = (size_t)BATCH * SEQ * HDIM;
        const size_t BH = (size_t)BATCH * HDIM;
        const size_t o  = (size_t)bb * HDIM + u0 + uu;
        out[OH + 0 * BH + o] = h0r;   // h layer 0
        out[OH + 1 * BH + o] = h1r;   // h layer 1
        out[OH + 2 * BH + o] = c0;    // c layer 0
        out[OH + 3 * BH + o] = c1;    // c layer 1
    }
}

extern "C" void kernel_launch(void* const* d_in, const int* in_sizes, int n_in,
                              void* d_out, int out_size) {
    const float* x  = (const float*)d_in[0];
    const float* W0 = (const float*)d_in[1];
    const float* b0 = (const float*)d_in[2];
    const float* W1 = (const float*)d_in[3];
    const float* b1 = (const float*)d_in[4];
    float* out = (float*)d_out;

    const int smem_floats = ROWS * P0 + ROWS * P1 + BATCH * P1 +
                            KGRP * SLAB + 64;
    const int smem_bytes = smem_floats * (int)sizeof(float);

    cudaFuncSetAttribute(lstm2_persistent,
                         cudaFuncAttributeMaxDynamicSharedMemorySize,
                         smem_bytes);

    lstm2_persistent<<<NCTA, NTHREADS, smem_bytes>>>(x, W0, b0, W1, b1, out);
}

// round 10
// speedup vs baseline: 1.3790x; 1.0468x over previous
#include <cuda_runtime.h>
#include <math.h>

// ---------------------------------------------------------------------------
// 2-layer LSTM, B=16, S=2048, I=256, H=512, fp32.
// Persistent kernel, 128 CTAs (1/SM), weights pinned in SMEM.
// R9: software-pipelined layers -> ONE global communication round per step.
//   Iteration i computes h0(i) AND h1(i-1) from a single staged h0(i-1):
//     A = [ x(i) | h0(i-1) | h1(i-2) ]   (one buffer, pitch 1282)
//     gates0(i)   = W0 @ A[:, 0:768]
//     gates1(i-1) = W1 @ A[:, 256:1280]
//   h0 publish is on the critical path; h1 publish has a full step of slack.
// ---------------------------------------------------------------------------

#define BATCH 16
#define SEQ   2048
#define IDIM  256
#define HDIM  512
#define NCTA  128
#define NTHREADS 256
#define ROWS  16          // 4 units x 4 gates per CTA, per layer
#define UNITS 4
#define K0    768         // I + H
#define K1    1024        // H + H
#define P0    770         // weight pitch L0 (4*P0 % 32 == 8 -> bank set {0,8,16,24})
#define P1    1026        // weight pitch L1
#define PA    1282        // combined A pitch (4*PA % 32 == 8)
#define KGRP  16          // split-K groups
#define SLAB  264         // padded partial slab

// ---- global scratch ----
__device__ __align__(16) float g_h0[2][BATCH * HDIM];
__device__ __align__(16) float g_h1[2][BATCH * HDIM];
__device__ unsigned int g_f0[NCTA];     // f0 = fbase+j+1  <=> h0(j) published
__device__ unsigned int g_f1[NCTA];     // f1 = fbase+j+1  <=> h1(j) published
__device__ unsigned int g_bar_count = 0;
__device__ volatile unsigned int g_bar_epoch = 0;

// ---- acquire/release helpers ----
__device__ __forceinline__ unsigned int ld_acq(const unsigned int* p) {
    unsigned int v;
    asm volatile("ld.acquire.gpu.u32 %0, [%1];" : "=r"(v) : "l"(p) : "memory");
    return v;
}
__device__ __forceinline__ void st_rel(unsigned int* p, unsigned int v) {
    asm volatile("st.release.gpu.u32 [%0], %1;" :: "l"(p), "r"(v) : "memory");
}

// one-time entry barrier (publishes zero-init); replay-safe monotone epoch
__device__ __forceinline__ void entry_barrier() {
    unsigned int ebase = 0;
    if (threadIdx.x == 0) ebase = g_bar_epoch;
    __syncthreads();
    if (threadIdx.x == 0) {
        __threadfence();
        unsigned int a = atomicAdd(&g_bar_count, 1u);
        unsigned int target = ebase + 1;
        if (a == NCTA - 1) {
            atomicExch(&g_bar_count, 0u);
            __threadfence();
            g_bar_epoch = target;
        } else {
            while ((int)(g_bar_epoch - target) < 0) { }
        }
        __threadfence();
    }
    __syncthreads();
}

// wait until ALL per-CTA flags reach target (parallel acquire-polls)
__device__ __forceinline__ void wait_flags(unsigned int* f, unsigned int target) {
    if (threadIdx.x < NCTA) {
        while ((int)(ld_acq(&f[threadIdx.x]) - target) < 0) { }
    }
    __syncthreads();
}

// ---- packed f32x2 FMA helpers ----
__device__ __forceinline__ void ffma2(unsigned long long& acc,
                                      unsigned long long a,
                                      unsigned long long b) {
    asm("fma.rn.f32x2 %0, %1, %2, %0;" : "+l"(acc) : "l"(a), "l"(b));
}
__device__ __forceinline__ float u2sum(unsigned long long v) {
    float lo, hi;
    asm("mov.b64 {%0,%1}, %2;" : "=f"(lo), "=f"(hi) : "l"(v));
    return lo + hi;
}

// ---- per-CTA GEMM: C[16 rows x 16 batch], 4x4 reg tile, split-K 16 ----
// k-pair index = kp*KGRP + kg (interleaved; kg stride 8B = 2 banks keeps the
// warp's combined bank set conflict-free against the 4-row {0,8,16,24} set).
template <int K, int WPITCH, int APITCH>
__device__ __forceinline__ void gemm16x16(const float* __restrict__ sW,
                                          const float* __restrict__ sA,
                                          float* __restrict__ sGp) {
    const int tid = threadIdx.x;
    const int kg  = tid >> 4;          // 0..15 split-K group
    const int t16 = tid & 15;
    const int tr  = t16 >> 2;          // rows 4tr..4tr+3
    const int tc  = t16 & 3;           // batches 4tc..4tc+3
    constexpr int KPG = (K / 2) / KGRP;   // 24 (K0) or 32 (K1)

    const unsigned long long* w0 = (const unsigned long long*)(sW + (4*tr+0)*WPITCH) + kg;
    const unsigned long long* w1 = (const unsigned long long*)(sW + (4*tr+1)*WPITCH) + kg;
    const unsigned long long* w2 = (const unsigned long long*)(sW + (4*tr+2)*WPITCH) + kg;
    const unsigned long long* w3 = (const unsigned long long*)(sW + (4*tr+3)*WPITCH) + kg;
    const unsigned long long* a0 = (const unsigned long long*)(sA + (4*tc+0)*APITCH) + kg;
    const unsigned long long* a1 = (const unsigned long long*)(sA + (4*tc+1)*APITCH) + kg;
    const unsigned long long* a2 = (const unsigned long long*)(sA + (4*tc+2)*APITCH) + kg;
    const unsigned long long* a3 = (const unsigned long long*)(sA + (4*tc+3)*APITCH) + kg;

    unsigned long long acc[4][4];
#pragma unroll
    for (int i = 0; i < 4; ++i)
#pragma unroll
        for (int j = 0; j < 4; ++j) acc[i][j] = 0ull;

#pragma unroll 4
    for (int kp = 0; kp < KPG; ++kp) {
        const int o = kp * KGRP;
        unsigned long long wv0 = w0[o], wv1 = w1[o], wv2 = w2[o], wv3 = w3[o];
        unsigned long long av0 = a0[o], av1 = a1[o], av2 = a2[o], av3 = a3[o];
        ffma2(acc[0][0], wv0, av0); ffma2(acc[0][1], wv0, av1);
        ffma2(acc[0][2], wv0, av2); ffma2(acc[0][3], wv0, av3);
        ffma2(acc[1][0], wv1, av0); ffma2(acc[1][1], wv1, av1);
        ffma2(acc[1][2], wv1, av2); ffma2(acc[1][3], wv1, av3);
        ffma2(acc[2][0], wv2, av0); ffma2(acc[2][1], wv2, av1);
        ffma2(acc[2][2], wv2, av2); ffma2(acc[2][3], wv2, av3);
        ffma2(acc[3][0], wv3, av0); ffma2(acc[3][1], wv3, av1);
        ffma2(acc[3][2], wv3, av2); ffma2(acc[3][3], wv3, av3);
    }

    float* dst = sGp + kg * SLAB;
#pragma unroll
    for (int i = 0; i < 4; ++i)
#pragma unroll
        for (int j = 0; j < 4; ++j)
            dst[(4*tr + i) * 16 + 4*tc + j] = u2sum(acc[i][j]);
}

__device__ __forceinline__ float sigmoidf_(float v) {
    return 1.0f / (1.0f + expf(-v));
}

__global__ void __launch_bounds__(NTHREADS, 1)
lstm2_persistent(const float* __restrict__ x,
                 const float* __restrict__ W0,
                 const float* __restrict__ b0,
                 const float* __restrict__ W1,
                 const float* __restrict__ b1,
                 float* __restrict__ out) {
    extern __shared__ float smem[];
    float* sW0  = smem;                        // 16*770
    float* sW1  = sW0 + ROWS * P0;             // 16*1026
    float* sAB  = sW1 + ROWS * P1;             // 16*1282  [x | h0 | h1]
    float* sGp0 = sAB + BATCH * PA;            // 16*264
    float* sGp1 = sGp0 + KGRP * SLAB;          // 16*264
    float* sB0  = sGp1 + KGRP * SLAB;          // 16
    float* sB1  = sB0 + 16;                    // 16

    const int m   = blockIdx.x;
    const int tid = threadIdx.x;
    const int u0  = m * UNITS;

    // ---- load persistent weight slices (row r = u*4 + gate) ----
    for (int idx = tid; idx < ROWS * (K0 / 2); idx += NTHREADS) {
        int r = idx / (K0 / 2), k2 = idx % (K0 / 2);
        int gg = r & 3, u = r >> 2;
        int grow = gg * HDIM + u0 + u;
        ((float2*)(sW0 + r * P0))[k2] =
            ((const float2*)(W0 + (size_t)grow * K0))[k2];
    }
    for (int idx = tid; idx < ROWS * (K1 / 2); idx += NTHREADS) {
        int r = idx / (K1 / 2), k2 = idx % (K1 / 2);
        int gg = r & 3, u = r >> 2;
        int grow = gg * HDIM + u0 + u;
        ((float2*)(sW1 + r * P1))[k2] =
            ((const float2*)(W1 + (size_t)grow * K1))[k2];
    }
    if (tid < ROWS) {
        int gg = tid & 3, u = tid >> 2;
        sB0[tid] = b0[gg * HDIM + u0 + u];
        sB1[tid] = b1[gg * HDIM + u0 + u];
    }

    const int uu = tid >> 4;                 // 0..3 unit (valid when tid<64)
    const int bb = tid & 15;                 // 0..15 batch
    float c0 = 0.f, c1 = 0.f, h0r = 0.f, h1r = 0.f;

    // replay-safe flag base (f0[m]==f1[m] at entry; stable until entry barrier)
    const unsigned int fbase = g_f0[m];

    // zero initial states: h0(-1) -> slot 1, h1(-1) -> slot 1
    if (tid < 64) {
        g_h0[1][bb * HDIM + u0 + uu] = 0.f;
        g_h1[1][bb * HDIM + u0 + uu] = 0.f;
    }
    entry_barrier();

    // Iteration i: computes h0(i) (if i<SEQ) and h1(i-1) (if i>0).
    for (int i = 0; i <= SEQ; ++i) {
        const unsigned int seq = fbase + (unsigned)i;

        // ---- stage x(i) (independent; overlaps any straggler wait) ----
        if (i < SEQ) {
            const float* xrow = x + (size_t)i * IDIM;
            for (int idx = tid; idx < BATCH * (IDIM / 2); idx += NTHREADS) {
                int b = idx >> 7, k = (idx & 127) * 2;
                *(float2*)(sAB + b * PA + k) =
                    *(const float2*)(xrow + (size_t)b * SEQ * IDIM + k);
            }
        }

        // ---- stage h1(i-2): slot (i-2)&1 == i&1 (cold wait, 1 step slack) --
        wait_flags(g_f1, seq - 1u);           // h1(i-2) published everywhere
        {
            const float* src = g_h1[i & 1];
            for (int idx = tid; idx < BATCH * (HDIM / 2); idx += NTHREADS) {
                int b = idx >> 8, k = (idx & 255) * 2;
                float2 v = __ldcg((const float2*)(src + b * HDIM + k));
                *(float2*)(sAB + b * PA + IDIM + HDIM + k) = v;
            }
        }

        // ---- stage h0(i-1): slot (i-1)&1 == (i+1)&1 (HOT wait) ----
        wait_flags(g_f0, seq);                // h0(i-1) published everywhere
        {
            const float* src = g_h0[(i + 1) & 1];
            for (int idx = tid; idx < BATCH * (HDIM / 2); idx += NTHREADS) {
                int b = idx >> 8, k = (idx & 255) * 2;
                float2 v = __ldcg((const float2*)(src + b * HDIM + k));
                *(float2*)(sAB + b * PA + IDIM + k) = v;
            }
        }
        __syncthreads();

        if (i < SEQ) gemm16x16<K0, P0, PA>(sW0, sAB, sGp0);
        if (i > 0)  gemm16x16<K1, P1, PA>(sW1, sAB + IDIM, sGp1);
        __syncthreads();

        if (tid < 64) {
            // ---- cell0 -> h0(i): publish FIRST (critical path) ----
            if (i < SEQ) {
                float g4[4];
#pragma unroll
                for (int gg = 0; gg < 4; ++gg) {
                    float r = sB0[uu * 4 + gg];
                    const int o = (uu * 4 + gg) * 16 + bb;
#pragma unroll
                    for (int s = 0; s < KGRP; ++s) r += sGp0[s * SLAB + o];
                    g4[gg] = r;
                }
                float ig = sigmoidf_(g4[0]);
                float fg = sigmoidf_(g4[1]);
                float cg = tanhf(g4[2]);
                float og = sigmoidf_(g4[3]);
                c0  = fg * c0 + ig * cg;
                h0r = og * tanhf(c0);
                g_h0[i & 1][bb * HDIM + u0 + uu] = h0r;
                __threadfence();
                asm volatile("bar.sync 1, 64;" ::: "memory");
                if (tid == 0) st_rel(&g_f0[m], seq + 1u);   // h0(i) live
            }
            // ---- cell1 -> h1(i-1): lazy publish ----
            if (i > 0) {
                float g4[4];
#pragma unroll
                for (int gg = 0; gg < 4; ++gg) {
                    float r = sB1[uu * 4 + gg];
                    const int o = (uu * 4 + gg) * 16 + bb;
#pragma unroll
                    for (int s = 0; s < KGRP; ++s) r += sGp1[s * SLAB + o];
                    g4[gg] = r;
                }
                float ig = sigmoidf_(g4[0]);
                float fg = sigmoidf_(g4[1]);
                float cg = tanhf(g4[2]);
                float og = sigmoidf_(g4[3]);
                c1  = fg * c1 + ig * cg;
                h1r = og * tanhf(c1);
                g_h1[(i - 1) & 1][bb * HDIM + u0 + uu] = h1r;
                out[((size_t)bb * SEQ + (i - 1)) * HDIM + u0 + uu] = h1r;
                __threadfence();
                asm volatile("bar.sync 2, 64;" ::: "memory");
                if (tid == 0) st_rel(&g_f1[m], seq);        // h1(i-1) live
            }
        }
        // no trailing sync: next staging writes sAB (gemm reads done at the
        // post-gemm sync); cell threads re-join at the next wait_flags sync.
    }

    // ---- final (h, c): [2,B,H] h then [2,B,H] c, after outputs[B,S,H] ----
    if (tid < 64) {
        const size_t OH = (size_t)BATCH * SEQ * HDIM;
        const size_t BH = (size_t)BATCH * HDIM;
        const size_t o  = (size_t)bb * HDIM + u0 + uu;
        out[OH + 0 * BH + o] = h0r;   // h layer 0
        out[OH + 1 * BH + o] = h1r;   // h layer 1
        out[OH + 2 * BH + o] = c0;    // c layer 0
        out[OH + 3 * BH + o] = c1;    // c layer 1
    }
}

extern "C" void kernel_launch(void* const* d_in, const int* in_sizes, int n_in,
                              void* d_out, int out_size) {
    const float* x  = (const float*)d_in[0];
    const float* W0 = (const float*)d_in[1];
    const float* b0 = (const float*)d_in[2];
    const float* W1 = (const float*)d_in[3];
    const float* b1 = (const float*)d_in[4];
    float* out = (float*)d_out;

    const int smem_floats = ROWS * P0 + ROWS * P1 + BATCH * PA +
                            2 * KGRP * SLAB + 32;
    const int smem_bytes = smem_floats * (int)sizeof(float);   // 230,912 B

    cudaFuncSetAttribute(lstm2_persistent,
                         cudaFuncAttributeMaxDynamicSharedMemorySize,
                         smem_bytes);

    lstm2_persistent<<<NCTA, NTHREADS, smem_bytes>>>(x, W0, b0, W1, b1, out);
}

// round 11
// speedup vs baseline: 1.4233x; 1.0321x over previous
#include <cuda_runtime.h>
#include <math.h>

// ---------------------------------------------------------------------------
// 2-layer LSTM, B=16, S=2048, I=256, H=512, fp32.
// Persistent kernel, 128 CTAs (1/SM), weights pinned in SMEM.
// R10: k-split the GEMMs around the hot dependence.
//   Iteration i computes h0(i) and h1(i-1).
//   PRE-WAIT (off recurrence):  acc0 += W0[:, :256] @ x(i)
//                               acc1 += W1[:, 512:] @ h1(i-2)
//   HOT (on recurrence):        acc0 += W0[:, 256:] @ h0(i-1)
//                               acc1 += W1[:, :512] @ h0(i-1)
//   Accumulators live in registers across the hot wait.
//   Publish path: STG -> bar.sync(64) -> st.release (no explicit membar).
//   Split-K partials shuffle-reduced in pairs before STS (8 slabs).
// ---------------------------------------------------------------------------

#define BATCH 16
#define SEQ   2048
#define IDIM  256
#define HDIM  512
#define NCTA  128
#define NTHREADS 256
#define ROWS  16          // 4 units x 4 gates per CTA, per layer
#define UNITS 4
#define K0    768
#define K1    1024
#define P0    770         // weight pitch L0 (4*P % 32 == 8 -> rows hit {0,8,16,24})
#define P1    1026        // weight pitch L1
#define PA    1282        // combined A pitch [x | h0 | h1]
#define KGRP  16          // split-K groups
#define SLAB  264         // padded partial slab
#define NSLAB 8           // slabs after in-warp pair reduction

// ---- global scratch ----
__device__ __align__(16) float g_h0[2][BATCH * HDIM];
__device__ __align__(16) float g_h1[2][BATCH * HDIM];
__device__ unsigned int g_f0[NCTA];     // f0 = fbase+j+1  <=> h0(j) published
__device__ unsigned int g_f1[NCTA];     // f1 = fbase+j+1  <=> h1(j) published
__device__ unsigned int g_bar_count = 0;
__device__ volatile unsigned int g_bar_epoch = 0;

// ---- acquire/release helpers ----
__device__ __forceinline__ unsigned int ld_acq(const unsigned int* p) {
    unsigned int v;
    asm volatile("ld.acquire.gpu.u32 %0, [%1];" : "=r"(v) : "l"(p) : "memory");
    return v;
}
__device__ __forceinline__ void st_rel(unsigned int* p, unsigned int v) {
    asm volatile("st.release.gpu.u32 [%0], %1;" :: "l"(p), "r"(v) : "memory");
}

// one-time entry barrier (publishes zero-init); replay-safe monotone epoch
__device__ __forceinline__ void entry_barrier() {
    unsigned int ebase = 0;
    if (threadIdx.x == 0) ebase = g_bar_epoch;
    __syncthreads();
    if (threadIdx.x == 0) {
        __threadfence();
        unsigned int a = atomicAdd(&g_bar_count, 1u);
        unsigned int target = ebase + 1;
        if (a == NCTA - 1) {
            atomicExch(&g_bar_count, 0u);
            __threadfence();
            g_bar_epoch = target;
        } else {
            while ((int)(g_bar_epoch - target) < 0) { }
        }
        __threadfence();
    }
    __syncthreads();
}

// wait until ALL per-CTA flags reach target (parallel acquire-polls)
__device__ __forceinline__ void wait_flags(unsigned int* f, unsigned int target) {
    if (threadIdx.x < NCTA) {
        while ((int)(ld_acq(&f[threadIdx.x]) - target) < 0) { }
    }
    __syncthreads();
}

// ---- packed f32x2 FMA helpers ----
__device__ __forceinline__ void ffma2(unsigned long long& acc,
                                      unsigned long long a,
                                      unsigned long long b) {
    asm("fma.rn.f32x2 %0, %1, %2, %0;" : "+l"(acc) : "l"(a), "l"(b));
}
__device__ __forceinline__ float u2sum(unsigned long long v) {
    float lo, hi;
    asm("mov.b64 {%0,%1}, %2;" : "=f"(lo), "=f"(hi) : "l"(v));
    return lo + hi;
}

// ---- accumulate a k-range into register tile: 4x4, split-K 16 ----
// base pointers pre-offset to the k-subrange start (offsets all ==0 mod 32
// floats, preserving the conflict-free bank pattern).
template <int KPG, int WPITCH, int APITCH>
__device__ __forceinline__ void gemm_acc(const float* __restrict__ sW,
                                         const float* __restrict__ sA,
                                         unsigned long long acc[4][4]) {
    const int tid = threadIdx.x;
    const int kg  = tid >> 4;          // 0..15 split-K group
    const int t16 = tid & 15;
    const int tr  = t16 >> 2;          // rows 4tr..4tr+3
    const int tc  = t16 & 3;           // batches 4tc..4tc+3

    const unsigned long long* w0 = (const unsigned long long*)(sW + (4*tr+0)*WPITCH) + kg;
    const unsigned long long* w1 = (const unsigned long long*)(sW + (4*tr+1)*WPITCH) + kg;
    const unsigned long long* w2 = (const unsigned long long*)(sW + (4*tr+2)*WPITCH) + kg;
    const unsigned long long* w3 = (const unsigned long long*)(sW + (4*tr+3)*WPITCH) + kg;
    const unsigned long long* a0 = (const unsigned long long*)(sA + (4*tc+0)*APITCH) + kg;
    const unsigned long long* a1 = (const unsigned long long*)(sA + (4*tc+1)*APITCH) + kg;
    const unsigned long long* a2 = (const unsigned long long*)(sA + (4*tc+2)*APITCH) + kg;
    const unsigned long long* a3 = (const unsigned long long*)(sA + (4*tc+3)*APITCH) + kg;

#pragma unroll 4
    for (int kp = 0; kp < KPG; ++kp) {
        const int o = kp * KGRP;       // interleaved split-K stride (128B)
        unsigned long long wv0 = w0[o], wv1 = w1[o], wv2 = w2[o], wv3 = w3[o];
        unsigned long long av0 = a0[o], av1 = a1[o], av2 = a2[o], av3 = a3[o];
        ffma2(acc[0][0], wv0, av0); ffma2(acc[0][1], wv0, av1);
        ffma2(acc[0][2], wv0, av2); ffma2(acc[0][3], wv0, av3);
        ffma2(acc[1][0], wv1, av0); ffma2(acc[1][1], wv1, av1);
        ffma2(acc[1][2], wv1, av2); ffma2(acc[1][3], wv1, av3);
        ffma2(acc[2][0], wv2, av0); ffma2(acc[2][1], wv2, av1);
        ffma2(acc[2][2], wv2, av2); ffma2(acc[2][3], wv2, av3);
        ffma2(acc[3][0], wv3, av0); ffma2(acc[3][1], wv3, av1);
        ffma2(acc[3][2], wv3, av2); ffma2(acc[3][3], wv3, av3);
    }
}

// reduce f32x2 halves + kg-pair shuffle-reduce, store to 8 slabs
__device__ __forceinline__ void store_acc(unsigned long long acc[4][4],
                                          float* __restrict__ sGp) {
    const int tid = threadIdx.x;
    const int kg  = tid >> 4;
    const int t16 = tid & 15;
    const int tr  = t16 >> 2;
    const int tc  = t16 & 3;
    float* dst = sGp + (kg >> 1) * SLAB;
    const bool lower = (tid & 16) == 0;   // kg even half of the warp
#pragma unroll
    for (int i = 0; i < 4; ++i)
#pragma unroll
        for (int j = 0; j < 4; ++j) {
            float v = u2sum(acc[i][j]);
            v += __shfl_xor_sync(0xffffffffu, v, 16);
            if (lower) dst[(4*tr + i) * 16 + 4*tc + j] = v;
        }
}

__device__ __forceinline__ float sigmoidf_(float v) {
    return 1.0f / (1.0f + expf(-v));
}

__global__ void __launch_bounds__(NTHREADS, 1)
lstm2_persistent(const float* __restrict__ x,
                 const float* __restrict__ W0,
                 const float* __restrict__ b0,
                 const float* __restrict__ W1,
                 const float* __restrict__ b1,
                 float* __restrict__ out) {
    extern __shared__ float smem[];
    float* sW0  = smem;                        // 16*770
    float* sW1  = sW0 + ROWS * P0;             // 16*1026
    float* sAB  = sW1 + ROWS * P1;             // 16*1282  [x | h0 | h1]
    float* sGp0 = sAB + BATCH * PA;            // 8*264
    float* sGp1 = sGp0 + NSLAB * SLAB;         // 8*264
    float* sB0  = sGp1 + NSLAB * SLAB;         // 16
    float* sB1  = sB0 + 16;                    // 16

    const int m   = blockIdx.x;
    const int tid = threadIdx.x;
    const int u0  = m * UNITS;

    // ---- load persistent weight slices (row r = u*4 + gate) ----
    for (int idx = tid; idx < ROWS * (K0 / 2); idx += NTHREADS) {
        int r = idx / (K0 / 2), k2 = idx % (K0 / 2);
        int gg = r & 3, u = r >> 2;
        int grow = gg * HDIM + u0 + u;
        ((float2*)(sW0 + r * P0))[k2] =
            ((const float2*)(W0 + (size_t)grow * K0))[k2];
    }
    for (int idx = tid; idx < ROWS * (K1 / 2); idx += NTHREADS) {
        int r = idx / (K1 / 2), k2 = idx % (K1 / 2);
        int gg = r & 3, u = r >> 2;
        int grow = gg * HDIM + u0 + u;
        ((float2*)(sW1 + r * P1))[k2] =
            ((const float2*)(W1 + (size_t)grow * K1))[k2];
    }
    if (tid < ROWS) {
        int gg = tid & 3, u = tid >> 2;
        sB0[tid] = b0[gg * HDIM + u0 + u];
        sB1[tid] = b1[gg * HDIM + u0 + u];
    }

    const int uu = tid >> 4;                 // 0..3 unit (valid when tid<64)
    const int bb = tid & 15;                 // 0..15 batch
    float c0 = 0.f, c1 = 0.f, h0r = 0.f, h1r = 0.f;

    const unsigned int fbase = g_f0[m];      // replay-safe (== g_f1[m] at entry)

    if (tid < 64) {
        g_h0[1][bb * HDIM + u0 + uu] = 0.f;  // h0(-1)
        g_h1[1][bb * HDIM + u0 + uu] = 0.f;  // h1(-1)
    }
    entry_barrier();

    // Iteration i: computes h0(i) (i<SEQ) and h1(i-1) (i>0).
    for (int i = 0; i <= SEQ; ++i) {
        const unsigned int seq = fbase + (unsigned)i;

        unsigned long long acc0[4][4], acc1[4][4];
#pragma unroll
        for (int a = 0; a < 4; ++a)
#pragma unroll
            for (int b = 0; b < 4; ++b) { acc0[a][b] = 0ull; acc1[a][b] = 0ull; }

        // ---- stage x(i) (no dependence) ----
        if (i < SEQ) {
            const float* xrow = x + (size_t)i * IDIM;
            for (int idx = tid; idx < BATCH * (IDIM / 2); idx += NTHREADS) {
                int b = idx >> 7, k = (idx & 127) * 2;
                *(float2*)(sAB + b * PA + k) =
                    *(const float2*)(xrow + (size_t)b * SEQ * IDIM + k);
            }
        }

        // ---- stage h1(i-2) (cold wait: one full step of slack) ----
        wait_flags(g_f1, seq - 1u);
        {
            const float* src = g_h1[i & 1];
            for (int idx = tid; idx < BATCH * (HDIM / 2); idx += NTHREADS) {
                int b = idx >> 8, k = (idx & 255) * 2;
                float2 v = __ldcg((const float2*)(src + b * HDIM + k));
                *(float2*)(sAB + b * PA + IDIM + HDIM + k) = v;
            }
        }
        __syncthreads();

        // ---- PRE-WAIT GEMM parts (off the hot recurrence) ----
        if (i < SEQ) gemm_acc<8,  P0, PA>(sW0, sAB, acc0);                      // W0 @ x
        if (i > 0)  gemm_acc<16, P1, PA>(sW1 + HDIM, sAB + IDIM + HDIM, acc1);  // W1 @ h1

        // ---- HOT: wait h0(i-1), stage it, finish both GEMMs ----
        wait_flags(g_f0, seq);
        {
            const float* src = g_h0[(i + 1) & 1];
            for (int idx = tid; idx < BATCH * (HDIM / 2); idx += NTHREADS) {
                int b = idx >> 8, k = (idx & 255) * 2;
                float2 v = __ldcg((const float2*)(src + b * HDIM + k));
                *(float2*)(sAB + b * PA + IDIM + k) = v;
            }
        }
        __syncthreads();

        if (i < SEQ) gemm_acc<16, P0, PA>(sW0 + IDIM, sAB + IDIM, acc0);  // W0 @ h0
        if (i > 0)  gemm_acc<16, P1, PA>(sW1,        sAB + IDIM, acc1);   // W1 @ h0

        if (i < SEQ) store_acc(acc0, sGp0);
        if (i > 0)  store_acc(acc1, sGp1);
        __syncthreads();

        if (tid < 64) {
            // ---- cell0 -> h0(i): publish FIRST (critical path) ----
            if (i < SEQ) {
                float g4[4];
#pragma unroll
                for (int gg = 0; gg < 4; ++gg) {
                    float r = sB0[uu * 4 + gg];
                    const int o = (uu * 4 + gg) * 16 + bb;
#pragma unroll
                    for (int s = 0; s < NSLAB; ++s) r += sGp0[s * SLAB + o];
                    g4[gg] = r;
                }
                float ig = sigmoidf_(g4[0]);
                float fg = sigmoidf_(g4[1]);
                float cg = tanhf(g4[2]);
                float og = sigmoidf_(g4[3]);
                c0  = fg * c0 + ig * cg;
                h0r = og * tanhf(c0);
                g_h0[i & 1][bb * HDIM + u0 + uu] = h0r;
                asm volatile("bar.sync 1, 64;" ::: "memory");  // 64-thread join
                if (tid == 0) st_rel(&g_f0[m], seq + 1u);      // h0(i) live
            }
            // ---- cell1 -> h1(i-1): lazy publish ----
            if (i > 0) {
                float g4[4];
#pragma unroll
                for (int gg = 0; gg < 4; ++gg) {
                    float r = sB1[uu * 4 + gg];
                    const int o = (uu * 4 + gg) * 16 + bb;
#pragma unroll
                    for (int s = 0; s < NSLAB; ++s) r += sGp1[s * SLAB + o];
                    g4[gg] = r;
                }
                float ig = sigmoidf_(g4[0]);
                float fg = sigmoidf_(g4[1]);
                float cg = tanhf(g4[2]);
                float og = sigmoidf_(g4[3]);
                c1  = fg * c1 + ig * cg;
                h1r = og * tanhf(c1);
                g_h1[(i - 1) & 1][bb * HDIM + u0 + uu] = h1r;
                out[((size_t)bb * SEQ + (i - 1)) * HDIM + u0 + uu] = h1r;
                asm volatile("bar.sync 2, 64;" ::: "memory");
                if (tid == 0) st_rel(&g_f1[m], seq);           // h1(i-1) live
            }
        }
        // no trailing sync needed: next iteration's first write to shared
        // state (x region) races nothing (all gemm reads of x finished
        // before the post-store __syncthreads above).
    }

    // ---- final (h, c): [2,B,H] h then [2,B,H] c, after outputs[B,S,H] ----
    if (tid < 64) {
        const size_t OH = (size_t)BATCH * SEQ * HDIM;
        const size_t BH = (size_t)BATCH * HDIM;
        const size_t o  = (size_t)bb * HDIM + u0 + uu;
        out[OH + 0 * BH + o] = h0r;   // h layer 0
        out[OH + 1 * BH + o] = h1r;   // h layer 1
        out[OH + 2 * BH + o] = c0;    // c layer 0
        out[OH + 3 * BH + o] = c1;    // c layer 1
    }
}

extern "C" void kernel_launch(void* const* d_in, const int* in_sizes, int n_in,
                              void* d_out, int out_size) {
    const float* x  = (const float*)d_in[0];
    const float* W0 = (const float*)d_in[1];
    const float* b0 = (const float*)d_in[2];
    const float* W1 = (const float*)d_in[3];
    const float* b1 = (const float*)d_in[4];
    float* out = (float*)d_out;

    const int smem_floats = ROWS * P0 + ROWS * P1 + BATCH * PA +
                            2 * NSLAB * SLAB + 32;
    const int smem_bytes = smem_floats * (int)sizeof(float);   // ~214 KB

    cudaFuncSetAttribute(lstm2_persistent,
                         cudaFuncAttributeMaxDynamicSharedMemorySize,
                         smem_bytes);

    lstm2_persistent<<<NCTA, NTHREADS, smem_bytes>>>(x, W0, b0, W1, b1, out);
}